// round 3
// baseline (speedup 1.0000x reference)
#include <cuda_runtime.h>
#include <cuda_bf16.h>
#include <cstdint>

// ---------------- problem constants ----------------
#define Nn 4096
#define Mm 4096
#define Dd 1024

// ---------------- GEMM tiling ----------------
#define BM 128
#define BN 256
#define BK 32
#define SKEW 8
#define BKP (BK + SKEW)            // 40 bf16 = 80B rows, ldmatrix conflict-free
#define KT (Dd / BK)               // 32
#define NSPLIT 4
#define NT (Nn / NSPLIT / BN)      // 4 n-tiles per CTA
#define ITER (NT * KT)             // 128
#define STAGES 5

#define A_SZ (BM * BKP * 2)        // 10240 B
#define B_SZ (BN * BKP * 2)        // 20480 B
#define STG (A_SZ + B_SZ)          // 30720 B
#define DYN_SMEM (STAGES * STG + 128)

// ---------------- scratch ----------------
__device__ __align__(256) __nv_bfloat16 g_zb[Nn * Dd];
__device__ __align__(256) __nv_bfloat16 g_eb[Mm * Dd];
__device__ __align__(256) float g_zsq[Nn];
__device__ __align__(256) float g_esq[Mm];
__device__ __align__(256) float g_partial[NSPLIT * Mm];

// ---------------- PTX helpers ----------------
__device__ __forceinline__ void cp_async16(uint32_t saddr, const void* gptr) {
    asm volatile("cp.async.cg.shared.global [%0], [%1], 16;\n" ::"r"(saddr), "l"(gptr));
}
__device__ __forceinline__ void cp_commit() { asm volatile("cp.async.commit_group;\n"); }
template <int NW>
__device__ __forceinline__ void cp_wait() { asm volatile("cp.async.wait_group %0;\n" ::"n"(NW)); }

__device__ __forceinline__ void ldsm4(uint32_t& r0, uint32_t& r1, uint32_t& r2, uint32_t& r3,
                                      uint32_t saddr) {
    asm volatile("ldmatrix.sync.aligned.m8n8.x4.shared.b16 {%0,%1,%2,%3}, [%4];\n"
                 : "=r"(r0), "=r"(r1), "=r"(r2), "=r"(r3)
                 : "r"(saddr));
}
__device__ __forceinline__ void mma16816(float* c, const uint32_t* a, uint32_t b0, uint32_t b1) {
    asm volatile(
        "mma.sync.aligned.m16n8k16.row.col.f32.bf16.bf16.f32 "
        "{%0,%1,%2,%3}, {%4,%5,%6,%7}, {%8,%9}, {%0,%1,%2,%3};\n"
        : "+f"(c[0]), "+f"(c[1]), "+f"(c[2]), "+f"(c[3])
        : "r"(a[0]), "r"(a[1]), "r"(a[2]), "r"(a[3]), "r"(b0), "r"(b1));
}

// ================= kernel 1: convert + squared norms (warp-per-row) =================
__global__ void __launch_bounds__(256) convert_kernel(const float* __restrict__ z,
                                                      const float* __restrict__ e) {
    const int gwarp = (blockIdx.x * 256 + threadIdx.x) >> 5;
    const int lane = threadIdx.x & 31;
    const float* src;
    __nv_bfloat16* dst;
    float* sqo;
    if (gwarp < Nn) {
        src = z + (size_t)gwarp * Dd;
        dst = g_zb + (size_t)gwarp * Dd;
        sqo = g_zsq + gwarp;
    } else {
        const int r = gwarp - Nn;
        src = e + (size_t)r * Dd;
        dst = g_eb + (size_t)r * Dd;
        sqo = g_esq + r;
    }
    float s = 0.f;
    const float4* s4 = reinterpret_cast<const float4*>(src);
    uint2* d2 = reinterpret_cast<uint2*>(dst);
#pragma unroll
    for (int i = 0; i < 8; i++) {
        float4 v = s4[lane + 32 * i];
        __nv_bfloat162 p0 = __floats2bfloat162_rn(v.x, v.y);
        __nv_bfloat162 p1 = __floats2bfloat162_rn(v.z, v.w);
        uint2 w;
        w.x = *reinterpret_cast<unsigned*>(&p0);
        w.y = *reinterpret_cast<unsigned*>(&p1);
        d2[lane + 32 * i] = w;
        s += v.x * v.x + v.y * v.y + v.z * v.z + v.w * v.w;
    }
#pragma unroll
    for (int o = 16; o; o >>= 1) s += __shfl_xor_sync(0xffffffffu, s, o);
    if (lane == 0) *sqo = s;
}

// ================= kernel 2: mma.sync GEMM + fused row-min =================
// CTA: 128 e-rows x (4 n-tiles of 256 z-cols), 8 warps in 2x4 grid, warp tile 64x64.
// 5-stage cp.async pipeline flattened across all (nt, kt) iterations.
__global__ void __launch_bounds__(256, 1) gemm_min_kernel() {
    extern __shared__ char dyn_raw[];
    __shared__ float srm[4][BM];

    uint32_t smem = (uint32_t)__cvta_generic_to_shared(dyn_raw);
    smem = (smem + 127u) & ~127u;

    const int tid = threadIdx.x;
    const int lane = tid & 31;
    const int warp = tid >> 5;
    const int wm = warp >> 2;        // 0..1 : 64-row group
    const int wn = warp & 3;         // 0..3 : 64-col group

    const int m0 = blockIdx.x * BM;
    const int split = blockIdx.y;
    const int n0base = split * (NT * BN);

    // cp.async mapping
    const int arow = tid >> 1;           // A: 128 rows, 2 threads/row
    const int aseg = (tid & 1) * 2;      // 2 consecutive 16B chunks
    // B: 256 rows, 1 thread/row, 4 chunks

    // ldmatrix lane mapping
    const int ldrow = lane & 15;
    const int ldcol = (lane >> 4) * 8;

    float acc[4][8][4];
    const float INF = __int_as_float(0x7f800000);
    float rm[4][2];
#pragma unroll
    for (int mi = 0; mi < 4; mi++) { rm[mi][0] = INF; rm[mi][1] = INF; }

    // ---- issue loads for logical iteration j into smem slot ----
    auto issue = [&](int j, int slot) {
        const int kt = j & (KT - 1);
        const int nt = j >> 5;
        const int k0 = kt * BK;
        const int n0 = n0base + nt * BN;
        const uint32_t sa = smem + slot * STG;
        const uint32_t sb = sa + A_SZ;
        {
            const __nv_bfloat16* g = g_eb + (size_t)(m0 + arow) * Dd + k0 + aseg * 8;
            const uint32_t d = sa + (uint32_t)(arow * BKP + aseg * 8) * 2;
            cp_async16(d, g);
            cp_async16(d + 16, g + 8);
        }
        {
            const __nv_bfloat16* g = g_zb + (size_t)(n0 + tid) * Dd + k0;
            const uint32_t d = sb + (uint32_t)(tid * BKP) * 2;
            cp_async16(d, g);
            cp_async16(d + 16, g + 8);
            cp_async16(d + 32, g + 16);
            cp_async16(d + 48, g + 24);
        }
    };

    // ---- prologue: fill STAGES-1 slots ----
#pragma unroll
    for (int j = 0; j < STAGES - 1; j++) {
        issue(j, j);
        cp_commit();
    }

    int slot = 0;        // compute slot
    int islot = STAGES - 1;  // issue slot

    for (int j = 0; j < ITER; j++) {
        cp_wait<STAGES - 2>();
        __syncthreads();

        // issue next tile (keep group count constant with empty commits at tail)
        if (j + STAGES - 1 < ITER) issue(j + STAGES - 1, islot);
        cp_commit();
        if (++islot == STAGES) islot = 0;

        const int kt = j & (KT - 1);
        if (kt == 0) {
#pragma unroll
            for (int mi = 0; mi < 4; mi++)
#pragma unroll
                for (int g = 0; g < 8; g++)
#pragma unroll
                    for (int q = 0; q < 4; q++) acc[mi][g][q] = 0.f;
        }

        const uint32_t sa = smem + slot * STG;
        const uint32_t sb = sa + A_SZ;
        if (++slot == STAGES) slot = 0;

#pragma unroll
        for (int ks = 0; ks < BK; ks += 16) {
            uint32_t a[4][4];
#pragma unroll
            for (int mi = 0; mi < 4; mi++) {
                const uint32_t addr =
                    sa + (uint32_t)((wm * 64 + mi * 16 + ldrow) * BKP + ks + ldcol) * 2;
                ldsm4(a[mi][0], a[mi][1], a[mi][2], a[mi][3], addr);
            }
#pragma unroll
            for (int gg = 0; gg < 4; gg++) {
                uint32_t b0, b1, b2, b3;
                const uint32_t addr =
                    sb + (uint32_t)((wn * 64 + gg * 16 + ldrow) * BKP + ks + ldcol) * 2;
                ldsm4(b0, b1, b2, b3, addr);
#pragma unroll
                for (int mi = 0; mi < 4; mi++) {
                    mma16816(acc[mi][2 * gg], a[mi], b0, b2);
                    mma16816(acc[mi][2 * gg + 1], a[mi], b1, b3);
                }
            }
        }

        if (kt == KT - 1) {
            // epilogue for this n-tile: fold zsq - 2*acc into register row-mins
            const int n0 = n0base + (j >> 5) * BN;
            const int colq = wn * 64 + (lane & 3) * 2;
#pragma unroll
            for (int g = 0; g < 8; g++) {
                const float2 zs = *reinterpret_cast<const float2*>(g_zsq + n0 + colq + g * 8);
#pragma unroll
                for (int mi = 0; mi < 4; mi++) {
                    const float v0 =
                        fminf(fmaf(-2.f, acc[mi][g][0], zs.x), fmaf(-2.f, acc[mi][g][1], zs.y));
                    const float v1 =
                        fminf(fmaf(-2.f, acc[mi][g][2], zs.x), fmaf(-2.f, acc[mi][g][3], zs.y));
                    rm[mi][0] = fminf(rm[mi][0], v0);
                    rm[mi][1] = fminf(rm[mi][1], v1);
                }
            }
        }
    }

    // ---- cross-lane reduce (lanes sharing a row differ in lane&3) ----
#pragma unroll
    for (int off = 1; off <= 2; off <<= 1) {
#pragma unroll
        for (int mi = 0; mi < 4; mi++) {
            rm[mi][0] = fminf(rm[mi][0], __shfl_xor_sync(0xffffffffu, rm[mi][0], off));
            rm[mi][1] = fminf(rm[mi][1], __shfl_xor_sync(0xffffffffu, rm[mi][1], off));
        }
    }
    __syncthreads();
    if ((lane & 3) == 0) {
        const int r = lane >> 2;
#pragma unroll
        for (int mi = 0; mi < 4; mi++) {
            srm[wn][wm * 64 + mi * 16 + r] = rm[mi][0];
            srm[wn][wm * 64 + mi * 16 + r + 8] = rm[mi][1];
        }
    }
    __syncthreads();
    if (tid < BM) {
        const float v = fminf(fminf(srm[0][tid], srm[1][tid]), fminf(srm[2][tid], srm[3][tid]));
        g_partial[split * Mm + m0 + tid] = v;
    }
}

// ================= kernel 3: finalize =================
__global__ void finalize_kernel(float* __restrict__ out) {
    const int t = threadIdx.x;  // 256
    float s = 0.f;
    for (int m = t; m < Mm; m += 256) {
        float mn = g_partial[m];
#pragma unroll
        for (int sp = 1; sp < NSPLIT; sp++) mn = fminf(mn, g_partial[sp * Mm + m]);
        s += mn + g_esq[m];
    }
#pragma unroll
    for (int off = 16; off; off >>= 1) s += __shfl_xor_sync(0xffffffffu, s, off);
    __shared__ float ws[8];
    if ((t & 31) == 0) ws[t >> 5] = s;
    __syncthreads();
    if (t == 0) {
        float tot = 0.f;
#pragma unroll
        for (int i = 0; i < 8; i++) tot += ws[i];
        out[0] = tot / (float)Mm;
    }
}

// ================= entry point =================
extern "C" void kernel_launch(void* const* d_in, const int* in_sizes, int n_in,
                              void* d_out, int out_size) {
    const float* z = (const float*)d_in[0];  // [4096, 1024]
    const float* e = (const float*)d_in[1];  // [4096, 1024]
    float* out = (float*)d_out;              // [1]

    convert_kernel<<<(Nn + Mm) / 8, 256>>>(z, e);

    static bool attr_set = false;
    if (!attr_set) {
        cudaFuncSetAttribute(gemm_min_kernel, cudaFuncAttributeMaxDynamicSharedMemorySize,
                             DYN_SMEM);
        attr_set = true;
    }
    dim3 grid(Mm / BM, NSPLIT);  // 32 x 4 = 128 CTAs
    gemm_min_kernel<<<grid, 256, DYN_SMEM>>>();

    finalize_kernel<<<1, 256>>>(out);
}

// round 4
// speedup vs baseline: 1.1729x; 1.1729x over previous
#include <cuda_runtime.h>
#include <cuda_bf16.h>
#include <cstdint>

// ---------------- problem constants ----------------
#define Nn 4096
#define Mm 4096
#define Dd 1024

// ---------------- GEMM tiling ----------------
#define BM 128
#define BN 128
#define BK 64
#define SKEW 8
#define BKP (BK + SKEW)            // 72 bf16 = 144B rows; ldmatrix conflict-free
#define KT (Dd / BK)               // 16 iterations per CTA
#define NSPLIT 32                  // n-tiles over z (BN each)
#define STAGES 3

#define A_SZ (BM * BKP * 2)        // 18432 B
#define B_SZ (BN * BKP * 2)        // 18432 B
#define STG (A_SZ + B_SZ)          // 36864 B
#define DYN_SMEM (STAGES * STG)    // 110592 B

// ---------------- scratch ----------------
__device__ __align__(256) __nv_bfloat16 g_zb[Nn * Dd];
__device__ __align__(256) __nv_bfloat16 g_eb[Mm * Dd];
__device__ __align__(256) float g_zsq[Nn];
__device__ __align__(256) float g_esq[Mm];
__device__ __align__(256) float g_partial[NSPLIT * Mm];

// ---------------- PTX helpers ----------------
__device__ __forceinline__ void cp_async16(uint32_t saddr, const void* gptr) {
    asm volatile("cp.async.cg.shared.global [%0], [%1], 16;\n" ::"r"(saddr), "l"(gptr));
}
__device__ __forceinline__ void cp_commit() { asm volatile("cp.async.commit_group;\n"); }
template <int NW>
__device__ __forceinline__ void cp_wait() { asm volatile("cp.async.wait_group %0;\n" ::"n"(NW)); }

__device__ __forceinline__ void ldsm4(uint32_t& r0, uint32_t& r1, uint32_t& r2, uint32_t& r3,
                                      uint32_t saddr) {
    asm volatile("ldmatrix.sync.aligned.m8n8.x4.shared.b16 {%0,%1,%2,%3}, [%4];\n"
                 : "=r"(r0), "=r"(r1), "=r"(r2), "=r"(r3)
                 : "r"(saddr));
}
__device__ __forceinline__ void mma16816(float* c, const uint32_t* a, uint32_t b0, uint32_t b1) {
    asm volatile(
        "mma.sync.aligned.m16n8k16.row.col.f32.bf16.bf16.f32 "
        "{%0,%1,%2,%3}, {%4,%5,%6,%7}, {%8,%9}, {%0,%1,%2,%3};\n"
        : "+f"(c[0]), "+f"(c[1]), "+f"(c[2]), "+f"(c[3])
        : "r"(a[0]), "r"(a[1]), "r"(a[2]), "r"(a[3]), "r"(b0), "r"(b1));
}

// ================= kernel 1: convert + squared norms (warp-per-row) =================
__global__ void __launch_bounds__(256) convert_kernel(const float* __restrict__ z,
                                                      const float* __restrict__ e) {
    const int gwarp = (blockIdx.x * 256 + threadIdx.x) >> 5;
    const int lane = threadIdx.x & 31;
    const float* src;
    __nv_bfloat16* dst;
    float* sqo;
    if (gwarp < Nn) {
        src = z + (size_t)gwarp * Dd;
        dst = g_zb + (size_t)gwarp * Dd;
        sqo = g_zsq + gwarp;
    } else {
        const int r = gwarp - Nn;
        src = e + (size_t)r * Dd;
        dst = g_eb + (size_t)r * Dd;
        sqo = g_esq + r;
    }
    float s = 0.f;
    const float4* s4 = reinterpret_cast<const float4*>(src);
    uint4* d4 = reinterpret_cast<uint4*>(dst);
#pragma unroll
    for (int i = 0; i < 4; i++) {
        const int idx = lane + 32 * i;      // 16B bf16 chunk index (8 values)
        float4 v0 = s4[2 * idx];
        float4 v1 = s4[2 * idx + 1];
        __nv_bfloat162 p0 = __floats2bfloat162_rn(v0.x, v0.y);
        __nv_bfloat162 p1 = __floats2bfloat162_rn(v0.z, v0.w);
        __nv_bfloat162 p2 = __floats2bfloat162_rn(v1.x, v1.y);
        __nv_bfloat162 p3 = __floats2bfloat162_rn(v1.z, v1.w);
        uint4 w;
        w.x = *reinterpret_cast<unsigned*>(&p0);
        w.y = *reinterpret_cast<unsigned*>(&p1);
        w.z = *reinterpret_cast<unsigned*>(&p2);
        w.w = *reinterpret_cast<unsigned*>(&p3);
        d4[idx] = w;
        s += v0.x * v0.x + v0.y * v0.y + v0.z * v0.z + v0.w * v0.w;
        s += v1.x * v1.x + v1.y * v1.y + v1.z * v1.z + v1.w * v1.w;
    }
#pragma unroll
    for (int o = 16; o; o >>= 1) s += __shfl_xor_sync(0xffffffffu, s, o);
    if (lane == 0) *sqo = s;
}

// ================= kernel 2: mma.sync GEMM + fused row-min =================
// CTA: 128 e-rows x 128 z-cols (one n-tile), full K=1024. 8 warps (4m x 2n),
// warp tile 32x64. 3-stage cp.async pipeline, one __syncthreads per BK=64 tile.
__global__ void __launch_bounds__(256, 2) gemm_min_kernel() {
    extern __shared__ char dyn_raw[];
    __shared__ float srm[2][BM];

    const uint32_t smem = (uint32_t)__cvta_generic_to_shared(dyn_raw);

    const int tid = threadIdx.x;
    const int lane = tid & 31;
    const int warp = tid >> 5;
    const int wm = warp >> 1;        // 0..3 : 32-row group
    const int wn = warp & 1;         // 0..1 : 64-col group

    const int m0 = blockIdx.x * BM;
    const int split = blockIdx.y;
    const int n0 = split * BN;

    // cp.async mapping: 128 rows, 2 threads/row, each thread 4 consecutive 16B chunks
    const int lrow = tid >> 1;
    const int lseg = (tid & 1) * 4;  // chunk index base (16B units)

    // ldmatrix lane mapping
    const int ldrow = lane & 15;
    const int ldcol = (lane >> 4) * 8;

    float acc[2][8][4];
#pragma unroll
    for (int mi = 0; mi < 2; mi++)
#pragma unroll
        for (int g = 0; g < 8; g++)
#pragma unroll
            for (int q = 0; q < 4; q++) acc[mi][g][q] = 0.f;

    // ---- issue loads for k-tile j into smem slot ----
    auto issue = [&](int j, int slot) {
        const int k0 = j * BK;
        const uint32_t sa = smem + slot * STG;
        const uint32_t sb = sa + A_SZ;
        const __nv_bfloat16* gA = g_eb + (size_t)(m0 + lrow) * Dd + k0 + lseg * 8;
        const __nv_bfloat16* gB = g_zb + (size_t)(n0 + lrow) * Dd + k0 + lseg * 8;
        const uint32_t dA = sa + (uint32_t)(lrow * BKP + lseg * 8) * 2;
        const uint32_t dB = sb + (uint32_t)(lrow * BKP + lseg * 8) * 2;
#pragma unroll
        for (int c = 0; c < 4; c++) {
            cp_async16(dA + c * 16, gA + c * 8);
            cp_async16(dB + c * 16, gB + c * 8);
        }
    };

    // ---- prologue: 2 stages in flight ----
    issue(0, 0);
    cp_commit();
    issue(1, 1);
    cp_commit();

    int cslot = 0, islot = 2;
    for (int j = 0; j < KT; j++) {
        cp_wait<1>();        // group j complete (only j+1 may pend)
        __syncthreads();     // all warps done with slot being overwritten + see j's data

        if (j + 2 < KT) issue(j + 2, islot);
        cp_commit();         // constant commit cadence (empty at tail)
        if (++islot == STAGES) islot = 0;

        const uint32_t sa = smem + cslot * STG;
        const uint32_t sb = sa + A_SZ;
        if (++cslot == STAGES) cslot = 0;

#pragma unroll
        for (int ks = 0; ks < BK; ks += 16) {
            uint32_t a[2][4];
#pragma unroll
            for (int mi = 0; mi < 2; mi++) {
                const uint32_t addr =
                    sa + (uint32_t)((wm * 32 + mi * 16 + ldrow) * BKP + ks + ldcol) * 2;
                ldsm4(a[mi][0], a[mi][1], a[mi][2], a[mi][3], addr);
            }
#pragma unroll
            for (int g = 0; g < 4; g++) {
                uint32_t b0, b1, b2, b3;
                const uint32_t addr =
                    sb + (uint32_t)((wn * 64 + g * 16 + ldrow) * BKP + ks + ldcol) * 2;
                ldsm4(b0, b1, b2, b3, addr);
#pragma unroll
                for (int mi = 0; mi < 2; mi++) {
                    mma16816(acc[mi][2 * g], a[mi], b0, b2);
                    mma16816(acc[mi][2 * g + 1], a[mi], b1, b3);
                }
            }
        }
    }

    // ---- epilogue: v = zsq[n] - 2*acc ; per-row min ----
    const float INF = __int_as_float(0x7f800000);
    float rm0 = INF, rm1 = INF, rm2 = INF, rm3 = INF;
    const int colbase = n0 + wn * 64 + (lane & 3) * 2;
#pragma unroll
    for (int g = 0; g < 8; g++) {
        const int col = colbase + g * 8;
        const float zs0 = g_zsq[col];
        const float zs1 = g_zsq[col + 1];
        {
            const float v0 = fminf(fmaf(-2.f, acc[0][g][0], zs0), fmaf(-2.f, acc[0][g][1], zs1));
            const float v1 = fminf(fmaf(-2.f, acc[0][g][2], zs0), fmaf(-2.f, acc[0][g][3], zs1));
            rm0 = fminf(rm0, v0);
            rm1 = fminf(rm1, v1);
        }
        {
            const float v0 = fminf(fmaf(-2.f, acc[1][g][0], zs0), fmaf(-2.f, acc[1][g][1], zs1));
            const float v1 = fminf(fmaf(-2.f, acc[1][g][2], zs0), fmaf(-2.f, acc[1][g][3], zs1));
            rm2 = fminf(rm2, v0);
            rm3 = fminf(rm3, v1);
        }
    }

    // reduce across the 4 lanes sharing each row
#pragma unroll
    for (int off = 1; off <= 2; off <<= 1) {
        rm0 = fminf(rm0, __shfl_xor_sync(0xffffffffu, rm0, off));
        rm1 = fminf(rm1, __shfl_xor_sync(0xffffffffu, rm1, off));
        rm2 = fminf(rm2, __shfl_xor_sync(0xffffffffu, rm2, off));
        rm3 = fminf(rm3, __shfl_xor_sync(0xffffffffu, rm3, off));
    }
    if ((lane & 3) == 0) {
        const int r = lane >> 2;
        srm[wn][wm * 32 + r] = rm0;
        srm[wn][wm * 32 + r + 8] = rm1;
        srm[wn][wm * 32 + 16 + r] = rm2;
        srm[wn][wm * 32 + 24 + r] = rm3;
    }
    __syncthreads();
    if (tid < BM) {
        g_partial[split * Mm + m0 + tid] = fminf(srm[0][tid], srm[1][tid]);
    }
}

// ================= kernel 3: finalize =================
__global__ void finalize_kernel(float* __restrict__ out) {
    const int t = threadIdx.x;  // 256
    float s = 0.f;
    for (int m = t; m < Mm; m += 256) {
        float mn = g_partial[m];
#pragma unroll
        for (int sp = 1; sp < NSPLIT; sp++) mn = fminf(mn, g_partial[sp * Mm + m]);
        s += mn + g_esq[m];
    }
#pragma unroll
    for (int off = 16; off; off >>= 1) s += __shfl_xor_sync(0xffffffffu, s, off);
    __shared__ float ws[8];
    if ((t & 31) == 0) ws[t >> 5] = s;
    __syncthreads();
    if (t == 0) {
        float tot = 0.f;
#pragma unroll
        for (int i = 0; i < 8; i++) tot += ws[i];
        out[0] = tot / (float)Mm;
    }
}

// ================= entry point =================
extern "C" void kernel_launch(void* const* d_in, const int* in_sizes, int n_in,
                              void* d_out, int out_size) {
    const float* z = (const float*)d_in[0];  // [4096, 1024]
    const float* e = (const float*)d_in[1];  // [4096, 1024]
    float* out = (float*)d_out;              // [1]

    convert_kernel<<<(Nn + Mm) / 8, 256>>>(z, e);

    static bool attr_set = false;
    if (!attr_set) {
        cudaFuncSetAttribute(gemm_min_kernel, cudaFuncAttributeMaxDynamicSharedMemorySize,
                             DYN_SMEM);
        attr_set = true;
    }
    dim3 grid(Mm / BM, NSPLIT);  // 32 x 32 = 1024 CTAs, 2/SM resident, dynamic refill
    gemm_min_kernel<<<grid, 256, DYN_SMEM>>>();

    finalize_kernel<<<1, 256>>>(out);
}